// round 1
// baseline (speedup 1.0000x reference)
#include <cuda_runtime.h>

// Problem constants (fixed by the dataset)
#define NN   100000
#define EE   1600000
#define RR   6
#define DIN  128
#define HH   64
#define SCAN_TPB 512
#define SCAN_EPB 2048                      // 512 threads * 4 elems
#define SCAN_NBLK ((NN + SCAN_EPB - 1) / SCAN_EPB)   // 49

// ---------------- device scratch (static; no runtime allocation) ------------
__device__ int   g_deg[NN];
__device__ int   g_hist[NN];
__device__ float g_dis[NN];
__device__ int   g_rowptr[NN + 1];
__device__ int   g_cursor[NN];
__device__ int   g_csr_src[EE];
__device__ float g_csr_w[EE];
__device__ int   g_bsums[64];

__device__ float g_tx1[(size_t)NN * DIN];
__device__ float g_tx2[(size_t)NN * DIN];
__device__ float g_h1 [(size_t)NN * HH];
__device__ float g_stack[(size_t)NN * RR * HH];
__device__ float g_G1   [(size_t)NN * RR * HH];
__device__ float g_hf[(size_t)NN * HH];
__device__ float g_P [(size_t)NN * HH];
__device__ float g_C [(size_t)NN * HH];

// ---------------- CSR build ---------------------------------------------

__global__ void k_zero_hists() {
    int i = blockIdx.x * blockDim.x + threadIdx.x;
    if (i < NN) { g_deg[i] = 0; g_hist[i] = 0; }
}

__global__ void k_hist(const int* __restrict__ src, const int* __restrict__ dst) {
    int e = blockIdx.x * blockDim.x + threadIdx.x;
    if (e < EE) {
        atomicAdd(&g_deg[src[e]], 1);
        atomicAdd(&g_hist[dst[e]], 1);
    }
}

__global__ void k_dis() {
    int i = blockIdx.x * blockDim.x + threadIdx.x;
    if (i < NN) {
        int d = g_deg[i];
        g_dis[i] = (d > 0) ? rsqrtf((float)d) : 0.0f;
    }
}

// block sums of hist
__global__ void k_scan1() {
    __shared__ int wsum[16];
    int tid = threadIdx.x, lane = tid & 31, wid = tid >> 5;
    int base = blockIdx.x * SCAN_EPB + tid * 4;
    int s = 0;
    #pragma unroll
    for (int i = 0; i < 4; i++) {
        int idx = base + i;
        if (idx < NN) s += g_hist[idx];
    }
    #pragma unroll
    for (int o = 16; o; o >>= 1) s += __shfl_xor_sync(0xffffffffu, s, o);
    if (lane == 0) wsum[wid] = s;
    __syncthreads();
    if (wid == 0) {
        int v = (lane < 16) ? wsum[lane] : 0;
        #pragma unroll
        for (int o = 8; o; o >>= 1) v += __shfl_xor_sync(0xffffffffu, v, o);
        if (lane == 0) g_bsums[blockIdx.x] = v;
    }
}

// serial exclusive scan of block sums (49 entries) + rowptr[N]=E
__global__ void k_scan2() {
    if (threadIdx.x == 0) {
        int run = 0;
        for (int i = 0; i < SCAN_NBLK; i++) {
            int t = g_bsums[i]; g_bsums[i] = run; run += t;
        }
        g_rowptr[NN] = EE;
    }
}

// full block exclusive scan -> rowptr + cursor
__global__ void k_scan3() {
    __shared__ int wsum[16];
    int tid = threadIdx.x, lane = tid & 31, wid = tid >> 5;
    int base = blockIdx.x * SCAN_EPB + tid * 4;
    int v[4];
    #pragma unroll
    for (int i = 0; i < 4; i++) {
        int idx = base + i;
        v[i] = (idx < NN) ? g_hist[idx] : 0;
    }
    int tsum = v[0] + v[1] + v[2] + v[3];
    int incl = tsum;
    #pragma unroll
    for (int o = 1; o < 32; o <<= 1) {
        int y = __shfl_up_sync(0xffffffffu, incl, o);
        if (lane >= o) incl += y;
    }
    if (lane == 31) wsum[wid] = incl;
    __syncthreads();
    if (wid == 0) {
        int w = (lane < 16) ? wsum[lane] : 0;
        #pragma unroll
        for (int o = 1; o < 16; o <<= 1) {
            int y = __shfl_up_sync(0xffffffffu, w, o);
            if (lane >= o) w += y;
        }
        if (lane < 16) wsum[lane] = w;
    }
    __syncthreads();
    int excl = incl - tsum + ((wid > 0) ? wsum[wid - 1] : 0) + g_bsums[blockIdx.x];
    #pragma unroll
    for (int i = 0; i < 4; i++) {
        int idx = base + i;
        if (idx < NN) { g_rowptr[idx] = excl; g_cursor[idx] = excl; }
        excl += v[i];
    }
}

__global__ void k_fill(const int* __restrict__ src, const int* __restrict__ dst) {
    int e = blockIdx.x * blockDim.x + threadIdx.x;
    if (e < EE) {
        int s = src[e], d = dst[e];
        float w = -(g_dis[s] * g_dis[d]);
        int pos = atomicAdd(&g_cursor[d], 1);
        g_csr_src[pos] = s;
        g_csr_w[pos] = w;
    }
}

// ---------------- SpMM: out[n] = alpha * sum_e w*v[src] + beta*base[n] ------

__global__ void k_spmm128(const float* __restrict__ v, const float* __restrict__ base,
                          float alpha, float beta, float* __restrict__ out) {
    int row = (blockIdx.x * blockDim.x + threadIdx.x) >> 5;
    int lane = threadIdx.x & 31;
    if (row >= NN) return;
    int e0 = g_rowptr[row], e1 = g_rowptr[row + 1];
    float4 acc = make_float4(0.f, 0.f, 0.f, 0.f);
    for (int eb = e0; eb < e1; eb += 32) {
        int idx = eb + lane;
        int   s = 0; float w = 0.f;
        if (idx < e1) { s = g_csr_src[idx]; w = g_csr_w[idx]; }
        int cnt = min(32, e1 - eb);
        #pragma unroll 4
        for (int j = 0; j < cnt; j++) {
            int   sj = __shfl_sync(0xffffffffu, s, j);
            float wj = __shfl_sync(0xffffffffu, w, j);
            float4 val = ((const float4*)(v + (size_t)sj * DIN))[lane];
            acc.x += wj * val.x; acc.y += wj * val.y;
            acc.z += wj * val.z; acc.w += wj * val.w;
        }
    }
    float4 o;
    if (base) {
        float4 b4 = ((const float4*)(base + (size_t)row * DIN))[lane];
        o.x = alpha * acc.x + beta * b4.x;
        o.y = alpha * acc.y + beta * b4.y;
        o.z = alpha * acc.z + beta * b4.z;
        o.w = alpha * acc.w + beta * b4.w;
    } else {
        o.x = alpha * acc.x; o.y = alpha * acc.y;
        o.z = alpha * acc.z; o.w = alpha * acc.w;
    }
    ((float4*)(out + (size_t)row * DIN))[lane] = o;
}

__global__ void k_spmm64(const float* __restrict__ v, const float* __restrict__ base,
                         float alpha, float beta, float* __restrict__ out) {
    int row = (blockIdx.x * blockDim.x + threadIdx.x) >> 5;
    int lane = threadIdx.x & 31;
    if (row >= NN) return;
    int e0 = g_rowptr[row], e1 = g_rowptr[row + 1];
    float2 acc = make_float2(0.f, 0.f);
    for (int eb = e0; eb < e1; eb += 32) {
        int idx = eb + lane;
        int   s = 0; float w = 0.f;
        if (idx < e1) { s = g_csr_src[idx]; w = g_csr_w[idx]; }
        int cnt = min(32, e1 - eb);
        #pragma unroll 4
        for (int j = 0; j < cnt; j++) {
            int   sj = __shfl_sync(0xffffffffu, s, j);
            float wj = __shfl_sync(0xffffffffu, w, j);
            float2 val = ((const float2*)(v + (size_t)sj * HH))[lane];
            acc.x += wj * val.x; acc.y += wj * val.y;
        }
    }
    float2 o;
    if (base) {
        float2 b2 = ((const float2*)(base + (size_t)row * HH))[lane];
        o.x = alpha * acc.x + beta * b2.x;
        o.y = alpha * acc.y + beta * b2.y;
    } else {
        o.x = alpha * acc.x; o.y = alpha * acc.y;
    }
    ((float2*)(out + (size_t)row * HH))[lane] = o;
}

// ---------------- GEMM: out = act( [A0|A1|A2] @ W + bias ) ------------------
// W: [NSEG*KSEG][64] row-major. 128-row x 64-col tile, 128 threads, 8x8/thread.
// Inner product uses packed fma.rn.f32x2 for 2x fp32 throughput.

template <int KSEG, int NSEG>
__global__ void __launch_bounds__(128)
k_gemm(const float* __restrict__ A0, const float* __restrict__ A1,
       const float* __restrict__ A2, const float* __restrict__ W,
       const float* __restrict__ bias, float* __restrict__ out,
       int ldout, int colofs, int nrows, int do_relu) {
    __shared__ float As[128][33];
    __shared__ float Bs[32][68];
    const int tid = threadIdx.x;
    const int tx = tid & 7;      // 8 col-groups of 8
    const int ty = tid >> 3;     // 16 row-groups of 8
    const int row0 = blockIdx.x * 128;
    constexpr int KTOT = KSEG * NSEG;

    unsigned long long acc[8][4];
    #pragma unroll
    for (int i = 0; i < 8; i++)
        #pragma unroll
        for (int j = 0; j < 4; j++) acc[i][j] = 0ull;

    for (int k0 = 0; k0 < KTOT; k0 += 32) {
        const float* Aseg = A0;
        if (NSEG > 1) {
            int s = k0 / KSEG;
            Aseg = (s == 0) ? A0 : ((s == 1) ? A1 : A2);
        }
        int kin = k0 % KSEG;
        // A tile: 128 x 32 (coalesced loads, conflict-free stores)
        #pragma unroll 8
        for (int l = 0; l < 32; l++) {
            int idx = l * 128 + tid;
            int r = idx >> 5, c = idx & 31;
            int grow = row0 + r;
            As[r][c] = (grow < nrows) ? Aseg[(size_t)grow * KSEG + kin + c] : 0.0f;
        }
        // B tile: 32 x 64
        #pragma unroll 8
        for (int l = 0; l < 16; l++) {
            int idx = l * 128 + tid;
            int r = idx >> 6, c = idx & 63;
            Bs[r][c] = W[(size_t)(k0 + r) * 64 + c];
        }
        __syncthreads();
        #pragma unroll
        for (int kk = 0; kk < 32; kk++) {
            unsigned long long b[4];
            const ulonglong2* bp = (const ulonglong2*)&Bs[kk][tx * 8];
            ulonglong2 b01 = bp[0];
            ulonglong2 b23 = bp[1];
            b[0] = b01.x; b[1] = b01.y; b[2] = b23.x; b[3] = b23.y;
            #pragma unroll
            for (int i = 0; i < 8; i++) {
                float a = As[ty * 8 + i][kk];
                unsigned long long a2;
                asm("mov.b64 %0, {%1, %1};" : "=l"(a2) : "f"(a));
                #pragma unroll
                for (int j = 0; j < 4; j++)
                    asm("fma.rn.f32x2 %0, %1, %2, %0;"
                        : "+l"(acc[i][j]) : "l"(a2), "l"(b[j]));
            }
        }
        __syncthreads();
    }
    // epilogue: bias + optional relu
    #pragma unroll
    for (int i = 0; i < 8; i++) {
        int grow = row0 + ty * 8 + i;
        if (grow < nrows) {
            float* orow = out + (size_t)grow * ldout + colofs + tx * 8;
            #pragma unroll
            for (int j = 0; j < 4; j++) {
                float2 v = *reinterpret_cast<float2*>(&acc[i][j]);
                int c = tx * 8 + j * 2;
                float r0 = v.x + bias[c];
                float r1 = v.y + bias[c + 1];
                if (do_relu) { r0 = fmaxf(r0, 0.f); r1 = fmaxf(r1, 0.f); }
                orow[j * 2] = r0;
                orow[j * 2 + 1] = r1;
            }
        }
    }
}

// ---------------- head: gate logits + softmax + fuse + aux ------------------
// one warp per node
__global__ void k_head(const float* __restrict__ G1, const float* __restrict__ stack,
                       const float* __restrict__ gate_w2, const float* __restrict__ gate_b2,
                       const float* __restrict__ aux_w, const float* __restrict__ aux_b,
                       float* __restrict__ hfused, float* __restrict__ aux_out) {
    int row = (blockIdx.x * blockDim.x + threadIdx.x) >> 5;
    int lane = threadIdx.x & 31;
    if (row >= NN) return;
    float2 w2 = ((const float2*)gate_w2)[lane];
    float gb2 = gate_b2[0];
    float logits[RR];
    float2 s[RR];
    #pragma unroll
    for (int r = 0; r < RR; r++) {
        float2 g = ((const float2*)(G1 + ((size_t)row * RR + r) * HH))[lane];
        s[r]     = ((const float2*)(stack + ((size_t)row * RR + r) * HH))[lane];
        float p = g.x * w2.x + g.y * w2.y;
        #pragma unroll
        for (int o = 16; o; o >>= 1) p += __shfl_xor_sync(0xffffffffu, p, o);
        logits[r] = p + gb2;
    }
    float m = logits[0];
    #pragma unroll
    for (int r = 1; r < RR; r++) m = fmaxf(m, logits[r]);
    float al[RR]; float sum = 0.f;
    #pragma unroll
    for (int r = 0; r < RR; r++) { al[r] = __expf(logits[r] - m); sum += al[r]; }
    float inv = 1.0f / sum;
    float2 hf = make_float2(0.f, 0.f);
    #pragma unroll
    for (int r = 0; r < RR; r++) {
        float a = al[r] * inv;
        hf.x += a * s[r].x;
        hf.y += a * s[r].y;
    }
    ((float2*)(hfused + (size_t)row * HH))[lane] = hf;
    #pragma unroll
    for (int r = 0; r < RR; r++) {
        float2 aw = ((const float2*)(aux_w + r * HH))[lane];
        float p = s[r].x * aw.x + s[r].y * aw.y;
        #pragma unroll
        for (int o = 16; o; o >>= 1) p += __shfl_xor_sync(0xffffffffu, p, o);
        if (lane == 0) aux_out[(size_t)row * RR + r] = p + aux_b[r];
    }
}

// final logit: warp per node
__global__ void k_final(const float* __restrict__ Cm, const float* __restrict__ w,
                        const float* __restrict__ b, float* __restrict__ out) {
    int row = (blockIdx.x * blockDim.x + threadIdx.x) >> 5;
    int lane = threadIdx.x & 31;
    if (row >= NN) return;
    float2 c = ((const float2*)(Cm + (size_t)row * HH))[lane];
    float2 wv = ((const float2*)w)[lane];
    float p = c.x * wv.x + c.y * wv.y;
    #pragma unroll
    for (int o = 16; o; o >>= 1) p += __shfl_xor_sync(0xffffffffu, p, o);
    if (lane == 0) out[row] = p + b[0];
}

// ---------------- launch ----------------------------------------------------

extern "C" void kernel_launch(void* const* d_in, const int* in_sizes, int n_in,
                              void* d_out, int out_size) {
    const float* x       = (const float*)d_in[0];
    const int*   ei      = (const int*)  d_in[1];
    const float* cheb1_w = (const float*)d_in[2];
    const float* cheb1_b = (const float*)d_in[3];
    const float* cheb2_w = (const float*)d_in[4];
    const float* cheb2_b = (const float*)d_in[5];
    const float* gate_w1 = (const float*)d_in[6];
    const float* gate_b1 = (const float*)d_in[7];
    const float* gate_w2 = (const float*)d_in[8];
    const float* gate_b2 = (const float*)d_in[9];
    const float* proj_w  = (const float*)d_in[10];
    const float* proj_b  = (const float*)d_in[11];
    const float* cls_w1  = (const float*)d_in[12];
    const float* cls_b1  = (const float*)d_in[13];
    const float* cls_w2  = (const float*)d_in[14];
    const float* cls_b2  = (const float*)d_in[15];
    const float* aux_w   = (const float*)d_in[16];
    const float* aux_b   = (const float*)d_in[17];
    float* out = (float*)d_out;

    float *tx1, *tx2, *h1, *stack, *G1, *hf, *P, *C;
    cudaGetSymbolAddress((void**)&tx1,   g_tx1);
    cudaGetSymbolAddress((void**)&tx2,   g_tx2);
    cudaGetSymbolAddress((void**)&h1,    g_h1);
    cudaGetSymbolAddress((void**)&stack, g_stack);
    cudaGetSymbolAddress((void**)&G1,    g_G1);
    cudaGetSymbolAddress((void**)&hf,    g_hf);
    cudaGetSymbolAddress((void**)&P,     g_P);
    cudaGetSymbolAddress((void**)&C,     g_C);

    const int nbN   = (NN + 255) / 256;
    const int nbE   = (EE + 255) / 256;
    const int nbW   = (NN * 32 + 255) / 256;       // warp-per-node kernels
    const int nbG   = (NN + 127) / 128;            // gemm over N rows
    const int nbG6  = (NN * RR + 127) / 128;       // gemm over N*R rows

    for (int r = 0; r < RR; r++) {
        const int* src = ei + ((size_t)r * 2 + 0) * EE;
        const int* dst = ei + ((size_t)r * 2 + 1) * EE;

        k_zero_hists<<<nbN, 256>>>();
        k_hist<<<nbE, 256>>>(src, dst);
        k_dis<<<nbN, 256>>>();
        k_scan1<<<SCAN_NBLK, SCAN_TPB>>>();
        k_scan2<<<1, 32>>>();
        k_scan3<<<SCAN_NBLK, SCAN_TPB>>>();
        k_fill<<<nbE, 256>>>(src, dst);

        // layer 1 (F = 128)
        k_spmm128<<<nbW, 256>>>(x,   nullptr, 1.0f,  0.0f, tx1);
        k_spmm128<<<nbW, 256>>>(tx1, x,       2.0f, -1.0f, tx2);
        k_gemm<128, 3><<<nbG, 128>>>(x, tx1, tx2,
                                     cheb1_w + (size_t)r * 3 * DIN * HH,
                                     cheb1_b + (size_t)r * HH,
                                     h1, HH, 0, NN, 1);

        // layer 2 (F = 64)
        k_spmm64<<<nbW, 256>>>(h1,  nullptr, 1.0f,  0.0f, tx1);
        k_spmm64<<<nbW, 256>>>(tx1, h1,      2.0f, -1.0f, tx2);
        k_gemm<64, 3><<<nbG, 128>>>(h1, tx1, tx2,
                                    cheb2_w + (size_t)r * 3 * HH * HH,
                                    cheb2_b + (size_t)r * HH,
                                    stack, RR * HH, r * HH, NN, 1);
    }

    // gate hidden: relu(stack2d @ gate_w1 + gate_b1), rows = N*R
    k_gemm<64, 1><<<nbG6, 128>>>(stack, nullptr, nullptr,
                                 gate_w1, gate_b1, G1, HH, 0, NN * RR, 1);
    // gate logits + softmax + fused + aux
    k_head<<<nbW, 256>>>(G1, stack, gate_w2, gate_b2, aux_w, aux_b,
                         hf, out + NN);
    // proj + cls
    k_gemm<64, 1><<<nbG, 128>>>(hf, nullptr, nullptr, proj_w, proj_b, P, HH, 0, NN, 1);
    k_gemm<64, 1><<<nbG, 128>>>(P,  nullptr, nullptr, cls_w1, cls_b1, C, HH, 0, NN, 1);
    k_final<<<nbW, 256>>>(C, cls_w2, cls_b2, out);
}

// round 15
// speedup vs baseline: 1.0879x; 1.0879x over previous
#include <cuda_runtime.h>
#include <cuda_fp16.h>

// Problem constants (fixed by the dataset)
#define NN   100000
#define EE   1600000
#define RR   6
#define DIN  128
#define HH   64
#define SCAN_TPB 512
#define SCAN_EPB 2048
#define SCAN_NBLK ((NN + SCAN_EPB - 1) / SCAN_EPB)   // 49

// ---------------- device scratch (static; no runtime allocation) ------------
__device__ int   g_deg[NN];
__device__ int   g_hist[NN];
__device__ float g_dis[NN];
__device__ int   g_rowptr[NN + 1];
__device__ int   g_cursor[NN];
__device__ int2  g_csr[EE];          // packed {src, __float_as_int(w)}
__device__ int   g_bsums[64];

__device__ float  g_tx1[(size_t)NN * DIN];
__device__ float  g_tx2[(size_t)NN * DIN];
__device__ float  g_h1 [(size_t)NN * HH];
__device__ __half g_xh [(size_t)NN * DIN];
__device__ __half g_uh [(size_t)NN * HH];
__device__ __half g_h1h[(size_t)NN * HH];
__device__ float  g_stack[(size_t)NN * RR * HH];
__device__ float  g_G1   [(size_t)NN * RR * HH];
__device__ float  g_hf[(size_t)NN * HH];
__device__ float  g_P [(size_t)NN * HH];
__device__ float  g_C [(size_t)NN * HH];
// combined weights: layer1 [W0-W2; W1] (256x64/rel), layer2 [W0'-W2'; W1'] (128x64/rel)
__device__ float  g_wc1[RR * 256 * 64];
__device__ float  g_wc2[RR * 128 * 64];

// ---------------- weight prep + quantize ------------------------------------

__global__ void k_prep(const float* __restrict__ c1w, const float* __restrict__ c2w) {
    int i = blockIdx.x * blockDim.x + threadIdx.x;
    const int n1 = RR * 256 * 64;
    const int n2 = RR * 128 * 64;
    if (i < n1) {
        int r = i / (256 * 64);
        int rem = i - r * 256 * 64;
        int row = rem >> 6, col = rem & 63;
        const float* base = c1w + (size_t)r * 3 * 128 * 64;
        float v;
        if (row < 128) v = base[row * 64 + col] - base[(2 * 128 + row) * 64 + col];
        else           v = base[(128 + (row - 128)) * 64 + col];
        g_wc1[i] = v;
    } else if (i < n1 + n2) {
        int j = i - n1;
        int r = j / (128 * 64);
        int rem = j - r * 128 * 64;
        int row = rem >> 6, col = rem & 63;
        const float* base = c2w + (size_t)r * 3 * 64 * 64;
        float v;
        if (row < 64) v = base[row * 64 + col] - base[(2 * 64 + row) * 64 + col];
        else          v = base[(64 + (row - 64)) * 64 + col];
        g_wc2[j] = v;
    }
}

__global__ void k_quant_x(const float* __restrict__ x) {
    int i = blockIdx.x * blockDim.x + threadIdx.x;
    if (i < NN * DIN / 4) {
        float4 a = ((const float4*)x)[i];
        __half2 lo = __floats2half2_rn(a.x, a.y);
        __half2 hi = __floats2half2_rn(a.z, a.w);
        ((__half2*)g_xh)[2 * i]     = lo;
        ((__half2*)g_xh)[2 * i + 1] = hi;
    }
}

// ---------------- CSR build --------------------------------------------------

__global__ void k_zero_hists() {
    int i = blockIdx.x * blockDim.x + threadIdx.x;
    if (i < NN) { g_deg[i] = 0; g_hist[i] = 0; }
}

__global__ void k_hist(const int* __restrict__ src, const int* __restrict__ dst) {
    int e = blockIdx.x * blockDim.x + threadIdx.x;
    if (e < EE) {
        atomicAdd(&g_deg[src[e]], 1);
        atomicAdd(&g_hist[dst[e]], 1);
    }
}

__global__ void k_dis() {
    int i = blockIdx.x * blockDim.x + threadIdx.x;
    if (i < NN) {
        int d = g_deg[i];
        g_dis[i] = (d > 0) ? rsqrtf((float)d) : 0.0f;
    }
}

__global__ void k_scan1() {
    __shared__ int wsum[16];
    int tid = threadIdx.x, lane = tid & 31, wid = tid >> 5;
    int base = blockIdx.x * SCAN_EPB + tid * 4;
    int s = 0;
    #pragma unroll
    for (int i = 0; i < 4; i++) {
        int idx = base + i;
        if (idx < NN) s += g_hist[idx];
    }
    #pragma unroll
    for (int o = 16; o; o >>= 1) s += __shfl_xor_sync(0xffffffffu, s, o);
    if (lane == 0) wsum[wid] = s;
    __syncthreads();
    if (wid == 0) {
        int v = (lane < 16) ? wsum[lane] : 0;
        #pragma unroll
        for (int o = 8; o; o >>= 1) v += __shfl_xor_sync(0xffffffffu, v, o);
        if (lane == 0) g_bsums[blockIdx.x] = v;
    }
}

__global__ void k_scan2() {
    if (threadIdx.x == 0) {
        int run = 0;
        for (int i = 0; i < SCAN_NBLK; i++) {
            int t = g_bsums[i]; g_bsums[i] = run; run += t;
        }
        g_rowptr[NN] = EE;
    }
}

__global__ void k_scan3() {
    __shared__ int wsum[16];
    int tid = threadIdx.x, lane = tid & 31, wid = tid >> 5;
    int base = blockIdx.x * SCAN_EPB + tid * 4;
    int v[4];
    #pragma unroll
    for (int i = 0; i < 4; i++) {
        int idx = base + i;
        v[i] = (idx < NN) ? g_hist[idx] : 0;
    }
    int tsum = v[0] + v[1] + v[2] + v[3];
    int incl = tsum;
    #pragma unroll
    for (int o = 1; o < 32; o <<= 1) {
        int y = __shfl_up_sync(0xffffffffu, incl, o);
        if (lane >= o) incl += y;
    }
    if (lane == 31) wsum[wid] = incl;
    __syncthreads();
    if (wid == 0) {
        int w = (lane < 16) ? wsum[lane] : 0;
        #pragma unroll
        for (int o = 1; o < 16; o <<= 1) {
            int y = __shfl_up_sync(0xffffffffu, w, o);
            if (lane >= o) w += y;
        }
        if (lane < 16) wsum[lane] = w;
    }
    __syncthreads();
    int excl = incl - tsum + ((wid > 0) ? wsum[wid - 1] : 0) + g_bsums[blockIdx.x];
    #pragma unroll
    for (int i = 0; i < 4; i++) {
        int idx = base + i;
        if (idx < NN) { g_rowptr[idx] = excl; g_cursor[idx] = excl; }
        excl += v[i];
    }
}

__global__ void k_fill(const int* __restrict__ src, const int* __restrict__ dst) {
    int e = blockIdx.x * blockDim.x + threadIdx.x;
    if (e < EE) {
        int s = src[e], d = dst[e];
        float w = -(g_dis[s] * g_dis[d]);
        int pos = atomicAdd(&g_cursor[d], 1);
        g_csr[pos] = make_int2(s, __float_as_int(w));
    }
}

// ---------------- SpMM (fp16 gather, fp32 accumulate): out = L @ v ----------

__global__ void k_spmm128h(const __half* __restrict__ v, float* __restrict__ out) {
    int row = (blockIdx.x * blockDim.x + threadIdx.x) >> 5;
    int lane = threadIdx.x & 31;
    if (row >= NN) return;
    int e0 = g_rowptr[row], e1 = g_rowptr[row + 1];
    float4 acc = make_float4(0.f, 0.f, 0.f, 0.f);
    for (int eb = e0; eb < e1; eb += 32) {
        int idx = eb + lane;
        int s = 0; float w = 0.f;
        if (idx < e1) { int2 rec = g_csr[idx]; s = rec.x; w = __int_as_float(rec.y); }
        int cnt = min(32, e1 - eb);
        #pragma unroll 4
        for (int j = 0; j < cnt; j++) {
            int   sj = __shfl_sync(0xffffffffu, s, j);
            float wj = __shfl_sync(0xffffffffu, w, j);
            uint2 p = ((const uint2*)(v + (size_t)sj * DIN))[lane];
            __half2 h0 = *reinterpret_cast<__half2*>(&p.x);
            __half2 h1 = *reinterpret_cast<__half2*>(&p.y);
            float2 f0 = __half22float2(h0);
            float2 f1 = __half22float2(h1);
            acc.x += wj * f0.x; acc.y += wj * f0.y;
            acc.z += wj * f1.x; acc.w += wj * f1.y;
        }
    }
    ((float4*)(out + (size_t)row * DIN))[lane] = acc;
}

__global__ void k_spmm64h(const __half* __restrict__ v, float* __restrict__ out) {
    int row = (blockIdx.x * blockDim.x + threadIdx.x) >> 5;
    int lane = threadIdx.x & 31;
    if (row >= NN) return;
    int e0 = g_rowptr[row], e1 = g_rowptr[row + 1];
    float2 acc = make_float2(0.f, 0.f);
    for (int eb = e0; eb < e1; eb += 32) {
        int idx = eb + lane;
        int s = 0; float w = 0.f;
        if (idx < e1) { int2 rec = g_csr[idx]; s = rec.x; w = __int_as_float(rec.y); }
        int cnt = min(32, e1 - eb);
        #pragma unroll 4
        for (int j = 0; j < cnt; j++) {
            int   sj = __shfl_sync(0xffffffffu, s, j);
            float wj = __shfl_sync(0xffffffffu, w, j);
            unsigned p = ((const unsigned*)(v + (size_t)sj * HH))[lane];
            float2 f = __half22float2(*reinterpret_cast<__half2*>(&p));
            acc.x += wj * f.x; acc.y += wj * f.y;
        }
    }
    ((float2*)(out + (size_t)row * HH))[lane] = acc;
}

// ---------------- GEMM: out = act( [A0|A1|A2] @ W + bias + 2*add ) ----------
// 128x64 tile, 128 threads, 8x8/thread, packed fma.rn.f32x2.

template <int KSEG, int NSEG>
__global__ void __launch_bounds__(128)
k_gemm(const float* __restrict__ A0, const float* __restrict__ A1,
       const float* __restrict__ A2, const float* __restrict__ W,
       const float* __restrict__ bias, const float* __restrict__ add,
       float* __restrict__ out, int ldout, int colofs,
       __half* __restrict__ out_h, int nrows, int do_relu) {
    __shared__ float As[128][33];
    __shared__ float Bs[32][68];
    const int tid = threadIdx.x;
    const int tx = tid & 7;
    const int ty = tid >> 3;
    const int row0 = blockIdx.x * 128;
    constexpr int KTOT = KSEG * NSEG;

    unsigned long long acc[8][4];
    #pragma unroll
    for (int i = 0; i < 8; i++)
        #pragma unroll
        for (int j = 0; j < 4; j++) acc[i][j] = 0ull;

    for (int k0 = 0; k0 < KTOT; k0 += 32) {
        const float* Aseg = A0;
        if (NSEG > 1) {
            int s = k0 / KSEG;
            Aseg = (s == 0) ? A0 : ((s == 1) ? A1 : A2);
        }
        int kin = k0 % KSEG;
        #pragma unroll 8
        for (int l = 0; l < 32; l++) {
            int idx = l * 128 + tid;
            int r = idx >> 5, c = idx & 31;
            int grow = row0 + r;
            As[r][c] = (grow < nrows) ? Aseg[(size_t)grow * KSEG + kin + c] : 0.0f;
        }
        #pragma unroll 8
        for (int l = 0; l < 16; l++) {
            int idx = l * 128 + tid;
            int r = idx >> 6, c = idx & 63;
            Bs[r][c] = W[(size_t)(k0 + r) * 64 + c];
        }
        __syncthreads();
        #pragma unroll
        for (int kk = 0; kk < 32; kk++) {
            unsigned long long b[4];
            const ulonglong2* bp = (const ulonglong2*)&Bs[kk][tx * 8];
            ulonglong2 b01 = bp[0];
            ulonglong2 b23 = bp[1];
            b[0] = b01.x; b[1] = b01.y; b[2] = b23.x; b[3] = b23.y;
            #pragma unroll
            for (int i = 0; i < 8; i++) {
                float a = As[ty * 8 + i][kk];
                unsigned long long a2;
                asm("mov.b64 %0, {%1, %1};" : "=l"(a2) : "f"(a));
                #pragma unroll
                for (int j = 0; j < 4; j++)
                    asm("fma.rn.f32x2 %0, %1, %2, %0;"
                        : "+l"(acc[i][j]) : "l"(a2), "l"(b[j]));
            }
        }
        __syncthreads();
    }
    float bregs[8];
    #pragma unroll
    for (int j = 0; j < 8; j++) bregs[j] = bias ? bias[tx * 8 + j] : 0.0f;
    #pragma unroll
    for (int i = 0; i < 8; i++) {
        int grow = row0 + ty * 8 + i;
        if (grow < nrows) {
            #pragma unroll
            for (int j = 0; j < 4; j++) {
                float2 v = *reinterpret_cast<float2*>(&acc[i][j]);
                float r0 = v.x + bregs[j * 2];
                float r1 = v.y + bregs[j * 2 + 1];
                if (add) {
                    float2 ad = ((const float2*)(add + (size_t)grow * 64 + tx * 8))[j];
                    r0 += 2.0f * ad.x; r1 += 2.0f * ad.y;
                }
                if (do_relu) { r0 = fmaxf(r0, 0.f); r1 = fmaxf(r1, 0.f); }
                if (out) {
                    float* orow = out + (size_t)grow * ldout + colofs + tx * 8;
                    orow[j * 2] = r0; orow[j * 2 + 1] = r1;
                }
                if (out_h) {
                    ((__half2*)(out_h + (size_t)grow * 64 + tx * 8))[j] =
                        __floats2half2_rn(r0, r1);
                }
            }
        }
    }
}

// ---------------- head: gate logits + softmax + fuse + aux ------------------

__global__ void k_head(const float* __restrict__ G1, const float* __restrict__ stack,
                       const float* __restrict__ gate_w2, const float* __restrict__ gate_b2,
                       const float* __restrict__ aux_w, const float* __restrict__ aux_b,
                       float* __restrict__ hfused, float* __restrict__ aux_out) {
    int row = (blockIdx.x * blockDim.x + threadIdx.x) >> 5;
    int lane = threadIdx.x & 31;
    if (row >= NN) return;
    float2 w2 = ((const float2*)gate_w2)[lane];
    float gb2 = gate_b2[0];
    float logits[RR];
    float2 s[RR];
    #pragma unroll
    for (int r = 0; r < RR; r++) {
        float2 g = ((const float2*)(G1 + ((size_t)row * RR + r) * HH))[lane];
        s[r]     = ((const float2*)(stack + ((size_t)row * RR + r) * HH))[lane];
        float p = g.x * w2.x + g.y * w2.y;
        #pragma unroll
        for (int o = 16; o; o >>= 1) p += __shfl_xor_sync(0xffffffffu, p, o);
        logits[r] = p + gb2;
    }
    float m = logits[0];
    #pragma unroll
    for (int r = 1; r < RR; r++) m = fmaxf(m, logits[r]);
    float al[RR]; float sum = 0.f;
    #pragma unroll
    for (int r = 0; r < RR; r++) { al[r] = __expf(logits[r] - m); sum += al[r]; }
    float inv = 1.0f / sum;
    float2 hf = make_float2(0.f, 0.f);
    #pragma unroll
    for (int r = 0; r < RR; r++) {
        float a = al[r] * inv;
        hf.x += a * s[r].x;
        hf.y += a * s[r].y;
    }
    ((float2*)(hfused + (size_t)row * HH))[lane] = hf;
    #pragma unroll
    for (int r = 0; r < RR; r++) {
        float2 aw = ((const float2*)(aux_w + r * HH))[lane];
        float p = s[r].x * aw.x + s[r].y * aw.y;
        #pragma unroll
        for (int o = 16; o; o >>= 1) p += __shfl_xor_sync(0xffffffffu, p, o);
        if (lane == 0) aux_out[(size_t)row * RR + r] = p + aux_b[r];
    }
}

__global__ void k_final(const float* __restrict__ Cm, const float* __restrict__ w,
                        const float* __restrict__ b, float* __restrict__ out) {
    int row = (blockIdx.x * blockDim.x + threadIdx.x) >> 5;
    int lane = threadIdx.x & 31;
    if (row >= NN) return;
    float2 c = ((const float2*)(Cm + (size_t)row * HH))[lane];
    float2 wv = ((const float2*)w)[lane];
    float p = c.x * wv.x + c.y * wv.y;
    #pragma unroll
    for (int o = 16; o; o >>= 1) p += __shfl_xor_sync(0xffffffffu, p, o);
    if (lane == 0) out[row] = p + b[0];
}

// ---------------- launch ----------------------------------------------------

extern "C" void kernel_launch(void* const* d_in, const int* in_sizes, int n_in,
                              void* d_out, int out_size) {
    const float* x       = (const float*)d_in[0];
    const int*   ei      = (const int*)  d_in[1];
    const float* cheb1_w = (const float*)d_in[2];
    const float* cheb1_b = (const float*)d_in[3];
    const float* cheb2_w = (const float*)d_in[4];
    const float* cheb2_b = (const float*)d_in[5];
    const float* gate_w1 = (const float*)d_in[6];
    const float* gate_b1 = (const float*)d_in[7];
    const float* gate_w2 = (const float*)d_in[8];
    const float* gate_b2 = (const float*)d_in[9];
    const float* proj_w  = (const float*)d_in[10];
    const float* proj_b  = (const float*)d_in[11];
    const float* cls_w1  = (const float*)d_in[12];
    const float* cls_b1  = (const float*)d_in[13];
    const float* cls_w2  = (const float*)d_in[14];
    const float* cls_b2  = (const float*)d_in[15];
    const float* aux_w   = (const float*)d_in[16];
    const float* aux_b   = (const float*)d_in[17];
    float* out = (float*)d_out;

    float *tx1, *tx2, *h1, *stack, *G1, *hf, *P, *C, *wc1, *wc2;
    __half *xh, *uh, *h1h;
    cudaGetSymbolAddress((void**)&tx1,   g_tx1);
    cudaGetSymbolAddress((void**)&tx2,   g_tx2);
    cudaGetSymbolAddress((void**)&h1,    g_h1);
    cudaGetSymbolAddress((void**)&stack, g_stack);
    cudaGetSymbolAddress((void**)&G1,    g_G1);
    cudaGetSymbolAddress((void**)&hf,    g_hf);
    cudaGetSymbolAddress((void**)&P,     g_P);
    cudaGetSymbolAddress((void**)&C,     g_C);
    cudaGetSymbolAddress((void**)&wc1,   g_wc1);
    cudaGetSymbolAddress((void**)&wc2,   g_wc2);
    cudaGetSymbolAddress((void**)&xh,    g_xh);
    cudaGetSymbolAddress((void**)&uh,    g_uh);
    cudaGetSymbolAddress((void**)&h1h,   g_h1h);

    const int nbN  = (NN + 255) / 256;
    const int nbE  = (EE + 255) / 256;
    const int nbW  = (NN * 32 + 255) / 256;
    const int nbG  = (NN + 127) / 128;
    const int nbG6 = (NN * RR + 127) / 128;
    const int nbP  = (RR * 256 * 64 + RR * 128 * 64 + 255) / 256;
    const int nbQ  = (NN * DIN / 4 + 255) / 256;

    k_prep<<<nbP, 256>>>(cheb1_w, cheb2_w);
    k_quant_x<<<nbQ, 256>>>(x);

    for (int r = 0; r < RR; r++) {
        const int* src = ei + ((size_t)r * 2 + 0) * EE;
        const int* dst = ei + ((size_t)r * 2 + 1) * EE;

        k_zero_hists<<<nbN, 256>>>();
        k_hist<<<nbE, 256>>>(src, dst);
        k_dis<<<nbN, 256>>>();
        k_scan1<<<SCAN_NBLK, SCAN_TPB>>>();
        k_scan2<<<1, 32>>>();
        k_scan3<<<SCAN_NBLK, SCAN_TPB>>>();
        k_fill<<<nbE, 256>>>(src, dst);

        // ---- layer 1 (ChebConv 128 -> 64), restructured:
        // z = Lx;  u = z@W2;  v = Lu;  h1 = relu([x|z]@[W0-W2;W1] + 2v + b)
        k_spmm128h<<<nbW, 256>>>(xh, tx1);                               // z
        k_gemm<128, 1><<<nbG, 128>>>(tx1, nullptr, nullptr,
                                     cheb1_w + (size_t)r * 3 * DIN * HH + 2 * DIN * HH,
                                     nullptr, nullptr, nullptr, HH, 0,
                                     uh, NN, 0);                          // u (fp16)
        k_spmm64h<<<nbW, 256>>>(uh, tx2);                                // v
        k_gemm<128, 2><<<nbG, 128>>>(x, tx1, nullptr,
                                     wc1 + (size_t)r * 256 * 64,
                                     cheb1_b + (size_t)r * HH, tx2,
                                     h1, HH, 0, h1h, NN, 1);             // h1 (+fp16)

        // ---- layer 2 (ChebConv 64 -> 64), same restructure
        k_spmm64h<<<nbW, 256>>>(h1h, tx1);                               // z2
        k_gemm<64, 1><<<nbG, 128>>>(tx1, nullptr, nullptr,
                                    cheb2_w + (size_t)r * 3 * HH * HH + 2 * HH * HH,
                                    nullptr, nullptr, nullptr, HH, 0,
                                    uh, NN, 0);                          // u2 (fp16)
        k_spmm64h<<<nbW, 256>>>(uh, tx2);                                // v2
        k_gemm<64, 2><<<nbG, 128>>>(h1, tx1, nullptr,
                                    wc2 + (size_t)r * 128 * 64,
                                    cheb2_b + (size_t)r * HH, tx2,
                                    stack, RR * HH, r * HH, nullptr, NN, 1);
    }

    // gate hidden: relu(stack2d @ gate_w1 + gate_b1), rows = N*R
    k_gemm<64, 1><<<nbG6, 128>>>(stack, nullptr, nullptr,
                                 gate_w1, gate_b1, nullptr,
                                 G1, HH, 0, nullptr, NN * RR, 1);
    k_head<<<nbW, 256>>>(G1, stack, gate_w2, gate_b2, aux_w, aux_b,
                         hf, out + NN);
    k_gemm<64, 1><<<nbG, 128>>>(hf, nullptr, nullptr, proj_w, proj_b, nullptr,
                                P, HH, 0, nullptr, NN, 1);
    k_gemm<64, 1><<<nbG, 128>>>(P, nullptr, nullptr, cls_w1, cls_b1, nullptr,
                                C, HH, 0, nullptr, NN, 1);
    k_final<<<nbW, 256>>>(C, cls_w2, cls_b2, out);
}